// round 15
// baseline (speedup 1.0000x reference)
#include <cuda_runtime.h>
#include <math_constants.h>

#define WML    64
#define BATCH  64
#define SENTS  40
#define DIM    512
#define NWORDS (SENTS * WML)   /* 2560 */
#define DYN_SMEM 32768         /* 4 warps x 4-slot ring x 2048B slots */

/* ------------------- scratch (static device memory; no allocs) -------- */
__device__ float g_qword[BATCH * DIM];
__device__ float g_qsent[BATCH * DIM];
__device__ float g_scores[BATCH * NWORDS];
__device__ float g_partM[BATCH * SENTS];
__device__ float g_partL[BATCH * SENTS];
__device__ float g_partAcc[(size_t)SENTS * BATCH * DIM];  /* 5.2 MB */
__device__ float g_c[BATCH * DIM];

__device__ __forceinline__ float dot4(float4 a, float4 b) {
    return a.x * b.x + a.y * b.y + a.z * b.z + a.w * b.w;
}

/* ------------------- K1: q projections — warp-per-output-column ------- */
/* 1024 warps (256 CTAs x 4). Warp g: matrix = g>>9, d = g&511. W row in */
/* registers; loop b 4-way unrolled (4 pipelined dot+shfl chains). src   */
/* is 128KB -> L1-resident per SM. Writes q directly (no partials).      */
__global__ void __launch_bounds__(128)
qproj_kernel(const float* __restrict__ src,
             const float* __restrict__ Wword,
             const float* __restrict__ Wsent) {
    const int wp = threadIdx.x >> 5, ln = threadIdx.x & 31;
    const int g = blockIdx.x * 4 + wp;
    const int which = g >> 9, d = g & 511;
    const float* W = which ? Wsent : Wword;
    float* out = which ? g_qsent : g_qword;

    const float4* Wr = (const float4*)(W + (size_t)d * DIM);
    const float4 w0 = Wr[ln], w1 = Wr[ln + 32], w2 = Wr[ln + 64], w3 = Wr[ln + 96];

    for (int b0 = 0; b0 < BATCH; b0 += 4) {
        float dots[4];
        #pragma unroll
        for (int u = 0; u < 4; u++) {
            const float4* A = (const float4*)(src + (size_t)(b0 + u) * DIM);
            dots[u] = dot4(A[ln], w0) + dot4(A[ln + 32], w1)
                    + dot4(A[ln + 64], w2) + dot4(A[ln + 96], w3);
        }
        #pragma unroll
        for (int u = 0; u < 4; u++) {
            #pragma unroll
            for (int off = 16; off > 0; off >>= 1)
                dots[u] += __shfl_xor_sync(0xffffffffu, dots[u], off);
        }
        if (ln < 4) out[(size_t)(b0 + ln) * DIM + d] = dots[ln];
    }
}

/* ------------------- per-warp row issue (self-loaded segments) -------- */
__device__ __forceinline__ void issue_row(const float* __restrict__ rowbase,
                                          size_t wstride, unsigned sbw,
                                          int k, int r, int ln) {
    const float* src = rowbase + (size_t)r * wstride;
    const unsigned dst = sbw + (unsigned)((k & 3) * 2048);   /* 2KB slot */
    #pragma unroll
    for (int j = 0; j < 4; j++)
        asm volatile("cp.async.cg.shared.global [%0], [%1], 16;\n"
                     :: "r"(dst + (unsigned)((ln + 32 * j) * 16)),
                        "l"(src + (ln + 32 * j) * 4));
    asm volatile("cp.async.commit_group;\n");
}

/* ------------------- K2: FUSED — 4 warps, warp-private ring ----------- */
__global__ void __launch_bounds__(128, 6)
fused_kernel(const float* __restrict__ word_bank,
             const int*   __restrict__ word_lengths,
             const float* __restrict__ sent_bank,
             const float* __restrict__ static_attn) {
    extern __shared__ float buf[];    /* [4 warps][4 slots][512]; 32KB */
    __shared__ float rm[4], rl[4];

    const int s = blockIdx.x, b = blockIdx.y;
    const int tid = threadIdx.x, wp = tid >> 5, ln = tid & 31;

    const int wl = word_lengths[b * SENTS + s];
    const int nk = (wl > wp) ? ((wl - wp + 3) >> 2) : 0;

    const size_t wstride = (size_t)BATCH * SENTS * DIM;
    const float* rowbase = word_bank + ((size_t)b * SENTS + s) * (size_t)DIM;
    float* bufw = buf + wp * 2048;
    const unsigned sbw = (unsigned)__cvta_generic_to_shared(bufw);

    /* prologue: get the stream going immediately */
    if (nk > 0) issue_row(rowbase, wstride, sbw, 0, wp,     ln);
    if (nk > 1) issue_row(rowbase, wstride, sbw, 1, wp + 4, ln);
    if (nk > 2) issue_row(rowbase, wstride, sbw, 2, wp + 8, ln);

    /* q (L1-resident after first warp) */
    const float4* qg = (const float4*)(g_qword + b * DIM);
    const float4 q0 = qg[ln], q1 = qg[ln + 32], q2 = qg[ln + 64], q3 = qg[ln + 96];

    /* inline ssa: every warp computes it redundantly (no sync needed) */
    float ssa;
    {
        const float4* qs = (const float4*)(g_qsent + b * DIM);
        const float4* sb = (const float4*)(sent_bank + ((size_t)s * BATCH + b) * DIM);
        float sd = dot4(qs[ln], sb[ln]) + dot4(qs[ln + 32], sb[ln + 32])
                 + dot4(qs[ln + 64], sb[ln + 64]) + dot4(qs[ln + 96], sb[ln + 96]);
        #pragma unroll
        for (int off = 16; off > 0; off >>= 1)
            sd += __shfl_xor_sync(0xffffffffu, sd, off);
        ssa = sd * static_attn[b * SENTS + s];
    }

    float m = -CUDART_INF_F, l = 0.f;
    float4 a0 = {0,0,0,0}, a1 = {0,0,0,0}, a2 = {0,0,0,0}, a3 = {0,0,0,0};

    for (int k = 0; k < nk; k++) {
        const int rem = nk - 1 - k;
        if (rem >= 2)      asm volatile("cp.async.wait_group 2;\n");
        else if (rem == 1) asm volatile("cp.async.wait_group 1;\n");
        else               asm volatile("cp.async.wait_group 0;\n");

        const float4* v4 = (const float4*)(bufw + (k & 3) * 512);
        float4 v0 = v4[ln], v1 = v4[ln + 32], v2 = v4[ln + 64], v3 = v4[ln + 96];
        float dot = dot4(v0, q0) + dot4(v1, q1) + dot4(v2, q2) + dot4(v3, q3);

        if (k + 3 < nk) issue_row(rowbase, wstride, sbw, k + 3, wp + 4 * (k + 3), ln);

        #pragma unroll
        for (int off = 16; off > 0; off >>= 1)
            dot += __shfl_xor_sync(0xffffffffu, dot, off);
        const float score = dot * ssa;
        if (ln == 0)
            g_scores[(size_t)b * NWORDS + s * WML + wp + 4 * k] = score;

        if (score > m) {           /* new max: p = 1, rescale old */
            const float scale = __expf(m - score);   /* first row: exp(-inf)=0 */
            l = l * scale + 1.f;
            a0.x = a0.x*scale + v0.x; a0.y = a0.y*scale + v0.y;
            a0.z = a0.z*scale + v0.z; a0.w = a0.w*scale + v0.w;
            a1.x = a1.x*scale + v1.x; a1.y = a1.y*scale + v1.y;
            a1.z = a1.z*scale + v1.z; a1.w = a1.w*scale + v1.w;
            a2.x = a2.x*scale + v2.x; a2.y = a2.y*scale + v2.y;
            a2.z = a2.z*scale + v2.z; a2.w = a2.w*scale + v2.w;
            a3.x = a3.x*scale + v3.x; a3.y = a3.y*scale + v3.y;
            a3.z = a3.z*scale + v3.z; a3.w = a3.w*scale + v3.w;
            m = score;
        } else {                   /* common path: no rescale */
            const float p = __expf(score - m);
            l += p;
            a0.x += p*v0.x; a0.y += p*v0.y; a0.z += p*v0.z; a0.w += p*v0.w;
            a1.x += p*v1.x; a1.y += p*v1.y; a1.z += p*v1.z; a1.w += p*v1.w;
            a2.x += p*v2.x; a2.y += p*v2.y; a2.z += p*v2.z; a2.w += p*v2.w;
            a3.x += p*v3.x; a3.y += p*v3.y; a3.z += p*v3.z; a3.w += p*v3.w;
        }
    }

    /* ---- 4-warp merge; reuse buf as racc[4][DIM] ---- */
    __syncthreads();
    float4* r4 = (float4*)(buf + wp * DIM);
    r4[ln] = a0; r4[ln + 32] = a1; r4[ln + 64] = a2; r4[ln + 96] = a3;
    if (ln == 0) { rm[wp] = m; rl[wp] = l; }
    __syncthreads();

    float mC = -CUDART_INF_F;
    #pragma unroll
    for (int i = 0; i < 4; i++) mC = fmaxf(mC, rm[i]);

    #pragma unroll
    for (int rr = 0; rr < 4; rr++) {
        const int d = tid + rr * 128;
        float sum = 0.f;
        #pragma unroll
        for (int i = 0; i < 4; i++) {
            const float sc = (rm[i] == -CUDART_INF_F) ? 0.f : __expf(rm[i] - mC);
            sum += buf[i * DIM + d] * sc;
        }
        g_partAcc[((size_t)s * BATCH + b) * DIM + d] = sum;
    }
    if (tid == 0) {
        float L = 0.f;
        #pragma unroll
        for (int i = 0; i < 4; i++) {
            const float sc = (rm[i] == -CUDART_INF_F) ? 0.f : __expf(rm[i] - mC);
            L += rl[i] * sc;
        }
        g_partM[b * SENTS + s] = mC;
        g_partL[b * SENTS + s] = L;
    }
}

/* ------------------- K3: combine partials -> c (y=0) / align (y=1) ---- */
__global__ void __launch_bounds__(512)
combine_kernel(const int* __restrict__ word_lengths,
               float* __restrict__ align_out, int has_align) {
    const int b = blockIdx.x, part = blockIdx.y, tid = threadIdx.x;
    const int wp = tid >> 5, ln = tid & 31;

    __shared__ float sScale[SENTS];
    __shared__ float sM, sinvL;

    if (wp == 0) {
        float m1 = g_partM[b * SENTS + ln];
        float m2 = (ln < SENTS - 32) ? g_partM[b * SENTS + 32 + ln] : -CUDART_INF_F;
        float mx = fmaxf(m1, m2);
        #pragma unroll
        for (int off = 16; off > 0; off >>= 1)
            mx = fmaxf(mx, __shfl_xor_sync(0xffffffffu, mx, off));
        const float sc1 = __expf(m1 - mx);
        const float sc2 = (ln < SENTS - 32) ? __expf(m2 - mx) : 0.f;
        float l = g_partL[b * SENTS + ln] * sc1;
        if (ln < SENTS - 32) l += g_partL[b * SENTS + 32 + ln] * sc2;
        #pragma unroll
        for (int off = 16; off > 0; off >>= 1)
            l += __shfl_xor_sync(0xffffffffu, l, off);
        sScale[ln] = sc1;
        if (ln < SENTS - 32) sScale[32 + ln] = sc2;
        if (ln == 0) { sM = mx; sinvL = 1.f / l; }
    }
    __syncthreads();
    const float M = sM, invL = sinvL;

    if (part == 0) {
        float csum = 0.f;
        #pragma unroll 8
        for (int s = 0; s < SENTS; s++)
            csum += sScale[s] * g_partAcc[((size_t)s * BATCH + b) * DIM + tid];
        g_c[b * DIM + tid] = csum * invL;
    } else if (has_align) {
        #pragma unroll
        for (int k = 0; k < 5; k++) {
            const int n = tid + k * 512;
            const int s = n >> 6, w = n & 63;
            float val = 1e-20f;
            if (w < word_lengths[b * SENTS + s])
                val = __expf(g_scores[(size_t)b * NWORDS + n] - M) * invL + 1e-20f;
            align_out[(size_t)b * NWORDS + n] = val;
        }
    }
}

/* ------------------- K4: out-proj + tanh — warp-per-output-column ----- */
/* 512 warps (128 CTAs x 4). Warp d: W_out row (4KB) in registers, loop  */
/* over b (2-way unrolled): dot over [c[b] | src[b]], tanh, store.       */
__global__ void __launch_bounds__(128)
outtanh_kernel(const float* __restrict__ src,
               const float* __restrict__ Wout,
               float* __restrict__ attn_out) {
    const int wp = threadIdx.x >> 5, ln = threadIdx.x & 31;
    const int d = blockIdx.x * 4 + wp;     /* 0..511 */

    const float4* Wr = (const float4*)(Wout + (size_t)d * (2 * DIM));
    float4 w[8];
    #pragma unroll
    for (int j = 0; j < 8; j++) w[j] = Wr[ln + 32 * j];

    for (int b0 = 0; b0 < BATCH; b0 += 2) {
        float dots[2];
        #pragma unroll
        for (int u = 0; u < 2; u++) {
            const int b = b0 + u;
            const float4* C4 = (const float4*)(g_c + (size_t)b * DIM);
            const float4* S4 = (const float4*)(src + (size_t)b * DIM);
            float dsum = 0.f;
            #pragma unroll
            for (int j = 0; j < 4; j++) dsum += dot4(C4[ln + 32 * j], w[j]);
            #pragma unroll
            for (int j = 0; j < 4; j++) dsum += dot4(S4[ln + 32 * j], w[4 + j]);
            dots[u] = dsum;
        }
        #pragma unroll
        for (int u = 0; u < 2; u++) {
            #pragma unroll
            for (int off = 16; off > 0; off >>= 1)
                dots[u] += __shfl_xor_sync(0xffffffffu, dots[u], off);
        }
        if (ln < 2) attn_out[(size_t)(b0 + ln) * DIM + d] = tanhf(dots[ln]);
    }
}

/* ------------------- launch ------------------------------------------- */
extern "C" void kernel_launch(void* const* d_in, const int* in_sizes, int n_in,
                              void* d_out, int out_size) {
    const float* source       = (const float*)d_in[0];
    const float* word_bank    = (const float*)d_in[1];
    const int*   word_lengths = (const int*)  d_in[2];
    const float* sent_bank    = (const float*)d_in[3];
    /* d_in[4] = sent_lengths: unused by forward math */
    const float* static_attn  = (const float*)d_in[5];
    const float* W_word       = (const float*)d_in[6];
    const float* W_sent       = (const float*)d_in[7];
    const float* W_out        = (const float*)d_in[8];

    float* attn_out  = (float*)d_out;
    const int need   = BATCH * DIM + BATCH * NWORDS;
    const int has_align = (out_size >= need) ? 1 : 0;
    float* align_out = attn_out + BATCH * DIM;

    cudaFuncSetAttribute(fused_kernel,
                         cudaFuncAttributeMaxDynamicSharedMemorySize, DYN_SMEM);

    qproj_kernel<<<256, 128>>>(source, W_word, W_sent);                  /* 1 */
    fused_kernel<<<dim3(SENTS, BATCH), 128, DYN_SMEM>>>(word_bank,
                     word_lengths, sent_bank, static_attn);              /* 2 */
    combine_kernel<<<dim3(BATCH, 2), 512>>>(word_lengths, align_out,
                                            has_align);                  /* 3 */
    outtanh_kernel<<<128, 128>>>(source, W_out, attn_out);               /* 4: profiled */
}

// round 16
// speedup vs baseline: 2.1131x; 2.1131x over previous
#include <cuda_runtime.h>
#include <math_constants.h>

#define WML    64
#define BATCH  64
#define SENTS  40
#define DIM    512
#define NWORDS (SENTS * WML)   /* 2560 */
#define DYN_SMEM 32768         /* 4 warps x 4-slot ring x 2048B slots */

/* ------------------- scratch (static device memory; no allocs) -------- */
__device__ float g_qword[BATCH * DIM];
__device__ float g_qsent[BATCH * DIM];
__device__ float g_scores[BATCH * NWORDS];
__device__ float g_partM[BATCH * SENTS];
__device__ float g_partL[BATCH * SENTS];
__device__ float g_partAcc[(size_t)SENTS * BATCH * DIM];  /* 5.2 MB */
__device__ float g_c[BATCH * DIM];

__device__ __forceinline__ float dot4(float4 a, float4 b) {
    return a.x * b.x + a.y * b.y + a.z * b.z + a.w * b.w;
}

/* ------------------- K1: q projections — warp-dot, 4096 warps --------- */
/* grid (256, 4). Warp g = bx*4+wp: which = g>>9, d = g&511. b-group of  */
/* 16 per blockIdx.y. W row (16 regs) stationary; 4-way-unrolled chains. */
__global__ void __launch_bounds__(128)
qproj_kernel(const float* __restrict__ src,
             const float* __restrict__ Wword,
             const float* __restrict__ Wsent) {
    const int wp = threadIdx.x >> 5, ln = threadIdx.x & 31;
    const int g = blockIdx.x * 4 + wp;
    const int which = g >> 9, d = g & 511;
    const int b0 = blockIdx.y * 16;
    const float* W = which ? Wsent : Wword;
    float* out = which ? g_qsent : g_qword;

    const float4* Wr = (const float4*)(W + (size_t)d * DIM);
    const float4 w0 = Wr[ln], w1 = Wr[ln + 32], w2 = Wr[ln + 64], w3 = Wr[ln + 96];

    for (int bb = b0; bb < b0 + 16; bb += 4) {
        float dots[4];
        #pragma unroll
        for (int u = 0; u < 4; u++) {
            const float4* A = (const float4*)(src + (size_t)(bb + u) * DIM);
            dots[u] = dot4(A[ln], w0) + dot4(A[ln + 32], w1)
                    + dot4(A[ln + 64], w2) + dot4(A[ln + 96], w3);
        }
        #pragma unroll
        for (int u = 0; u < 4; u++) {
            #pragma unroll
            for (int off = 16; off > 0; off >>= 1)
                dots[u] += __shfl_xor_sync(0xffffffffu, dots[u], off);
        }
        if (ln < 4) out[(size_t)(bb + ln) * DIM + d] = dots[ln];
    }
}

/* ------------------- per-warp row issue (self-loaded segments) -------- */
__device__ __forceinline__ void issue_row(const float* __restrict__ rowbase,
                                          size_t wstride, unsigned sbw,
                                          int k, int r, int ln) {
    const float* src = rowbase + (size_t)r * wstride;
    const unsigned dst = sbw + (unsigned)((k & 3) * 2048);   /* 2KB slot */
    #pragma unroll
    for (int j = 0; j < 4; j++)
        asm volatile("cp.async.cg.shared.global [%0], [%1], 16;\n"
                     :: "r"(dst + (unsigned)((ln + 32 * j) * 16)),
                        "l"(src + (ln + 32 * j) * 4));
    asm volatile("cp.async.commit_group;\n");
}

/* ------------------- K2: FUSED — 4 warps, warp-private ring ----------- */
__global__ void __launch_bounds__(128, 6)
fused_kernel(const float* __restrict__ word_bank,
             const int*   __restrict__ word_lengths,
             const float* __restrict__ sent_bank,
             const float* __restrict__ static_attn) {
    extern __shared__ float buf[];    /* [4 warps][4 slots][512]; 32KB */
    __shared__ float rm[4], rl[4];

    const int s = blockIdx.x, b = blockIdx.y;
    const int tid = threadIdx.x, wp = tid >> 5, ln = tid & 31;

    const int wl = word_lengths[b * SENTS + s];
    const int nk = (wl > wp) ? ((wl - wp + 3) >> 2) : 0;

    const size_t wstride = (size_t)BATCH * SENTS * DIM;
    const float* rowbase = word_bank + ((size_t)b * SENTS + s) * (size_t)DIM;
    float* bufw = buf + wp * 2048;
    const unsigned sbw = (unsigned)__cvta_generic_to_shared(bufw);

    /* prologue: get the stream going immediately */
    if (nk > 0) issue_row(rowbase, wstride, sbw, 0, wp,     ln);
    if (nk > 1) issue_row(rowbase, wstride, sbw, 1, wp + 4, ln);
    if (nk > 2) issue_row(rowbase, wstride, sbw, 2, wp + 8, ln);

    /* q (L1-resident after first warp) */
    const float4* qg = (const float4*)(g_qword + b * DIM);
    const float4 q0 = qg[ln], q1 = qg[ln + 32], q2 = qg[ln + 64], q3 = qg[ln + 96];

    /* inline ssa: every warp computes it redundantly (no sync needed) */
    float ssa;
    {
        const float4* qs = (const float4*)(g_qsent + b * DIM);
        const float4* sb = (const float4*)(sent_bank + ((size_t)s * BATCH + b) * DIM);
        float sd = dot4(qs[ln], sb[ln]) + dot4(qs[ln + 32], sb[ln + 32])
                 + dot4(qs[ln + 64], sb[ln + 64]) + dot4(qs[ln + 96], sb[ln + 96]);
        #pragma unroll
        for (int off = 16; off > 0; off >>= 1)
            sd += __shfl_xor_sync(0xffffffffu, sd, off);
        ssa = sd * static_attn[b * SENTS + s];
    }

    float m = -CUDART_INF_F, l = 0.f;
    float4 a0 = {0,0,0,0}, a1 = {0,0,0,0}, a2 = {0,0,0,0}, a3 = {0,0,0,0};

    for (int k = 0; k < nk; k++) {
        const int rem = nk - 1 - k;
        if (rem >= 2)      asm volatile("cp.async.wait_group 2;\n");
        else if (rem == 1) asm volatile("cp.async.wait_group 1;\n");
        else               asm volatile("cp.async.wait_group 0;\n");

        const float4* v4 = (const float4*)(bufw + (k & 3) * 512);
        float4 v0 = v4[ln], v1 = v4[ln + 32], v2 = v4[ln + 64], v3 = v4[ln + 96];
        float dot = dot4(v0, q0) + dot4(v1, q1) + dot4(v2, q2) + dot4(v3, q3);

        if (k + 3 < nk) issue_row(rowbase, wstride, sbw, k + 3, wp + 4 * (k + 3), ln);

        #pragma unroll
        for (int off = 16; off > 0; off >>= 1)
            dot += __shfl_xor_sync(0xffffffffu, dot, off);
        const float score = dot * ssa;
        if (ln == 0)
            g_scores[(size_t)b * NWORDS + s * WML + wp + 4 * k] = score;

        if (score > m) {           /* new max: p = 1, rescale old */
            const float scale = __expf(m - score);   /* first row: exp(-inf)=0 */
            l = l * scale + 1.f;
            a0.x = a0.x*scale + v0.x; a0.y = a0.y*scale + v0.y;
            a0.z = a0.z*scale + v0.z; a0.w = a0.w*scale + v0.w;
            a1.x = a1.x*scale + v1.x; a1.y = a1.y*scale + v1.y;
            a1.z = a1.z*scale + v1.z; a1.w = a1.w*scale + v1.w;
            a2.x = a2.x*scale + v2.x; a2.y = a2.y*scale + v2.y;
            a2.z = a2.z*scale + v2.z; a2.w = a2.w*scale + v2.w;
            a3.x = a3.x*scale + v3.x; a3.y = a3.y*scale + v3.y;
            a3.z = a3.z*scale + v3.z; a3.w = a3.w*scale + v3.w;
            m = score;
        } else {                   /* common path: no rescale */
            const float p = __expf(score - m);
            l += p;
            a0.x += p*v0.x; a0.y += p*v0.y; a0.z += p*v0.z; a0.w += p*v0.w;
            a1.x += p*v1.x; a1.y += p*v1.y; a1.z += p*v1.z; a1.w += p*v1.w;
            a2.x += p*v2.x; a2.y += p*v2.y; a2.z += p*v2.z; a2.w += p*v2.w;
            a3.x += p*v3.x; a3.y += p*v3.y; a3.z += p*v3.z; a3.w += p*v3.w;
        }
    }

    /* ---- 4-warp merge; reuse buf as racc[4][DIM] ---- */
    __syncthreads();
    float4* r4 = (float4*)(buf + wp * DIM);
    r4[ln] = a0; r4[ln + 32] = a1; r4[ln + 64] = a2; r4[ln + 96] = a3;
    if (ln == 0) { rm[wp] = m; rl[wp] = l; }
    __syncthreads();

    float mC = -CUDART_INF_F;
    #pragma unroll
    for (int i = 0; i < 4; i++) mC = fmaxf(mC, rm[i]);

    #pragma unroll
    for (int rr = 0; rr < 4; rr++) {
        const int d = tid + rr * 128;
        float sum = 0.f;
        #pragma unroll
        for (int i = 0; i < 4; i++) {
            const float sc = (rm[i] == -CUDART_INF_F) ? 0.f : __expf(rm[i] - mC);
            sum += buf[i * DIM + d] * sc;
        }
        g_partAcc[((size_t)s * BATCH + b) * DIM + d] = sum;
    }
    if (tid == 0) {
        float L = 0.f;
        #pragma unroll
        for (int i = 0; i < 4; i++) {
            const float sc = (rm[i] == -CUDART_INF_F) ? 0.f : __expf(rm[i] - mC);
            L += rl[i] * sc;
        }
        g_partM[b * SENTS + s] = mC;
        g_partL[b * SENTS + s] = L;
    }
}

/* ------------------- K3: combine partials -> c (y=0) / align (y=1) ---- */
__global__ void __launch_bounds__(512)
combine_kernel(const int* __restrict__ word_lengths,
               float* __restrict__ align_out, int has_align) {
    const int b = blockIdx.x, part = blockIdx.y, tid = threadIdx.x;
    const int wp = tid >> 5, ln = tid & 31;

    __shared__ float sScale[SENTS];
    __shared__ float sM, sinvL;

    if (wp == 0) {
        float m1 = g_partM[b * SENTS + ln];
        float m2 = (ln < SENTS - 32) ? g_partM[b * SENTS + 32 + ln] : -CUDART_INF_F;
        float mx = fmaxf(m1, m2);
        #pragma unroll
        for (int off = 16; off > 0; off >>= 1)
            mx = fmaxf(mx, __shfl_xor_sync(0xffffffffu, mx, off));
        const float sc1 = __expf(m1 - mx);
        const float sc2 = (ln < SENTS - 32) ? __expf(m2 - mx) : 0.f;
        float l = g_partL[b * SENTS + ln] * sc1;
        if (ln < SENTS - 32) l += g_partL[b * SENTS + 32 + ln] * sc2;
        #pragma unroll
        for (int off = 16; off > 0; off >>= 1)
            l += __shfl_xor_sync(0xffffffffu, l, off);
        sScale[ln] = sc1;
        if (ln < SENTS - 32) sScale[32 + ln] = sc2;
        if (ln == 0) { sM = mx; sinvL = 1.f / l; }
    }
    __syncthreads();
    const float M = sM, invL = sinvL;

    if (part == 0) {
        float csum = 0.f;
        #pragma unroll 8
        for (int s = 0; s < SENTS; s++)
            csum += sScale[s] * g_partAcc[((size_t)s * BATCH + b) * DIM + tid];
        g_c[b * DIM + tid] = csum * invL;
    } else if (has_align) {
        #pragma unroll
        for (int k = 0; k < 5; k++) {
            const int n = tid + k * 512;
            const int s = n >> 6, w = n & 63;
            float val = 1e-20f;
            if (w < word_lengths[b * SENTS + s])
                val = __expf(g_scores[(size_t)b * NWORDS + n] - M) * invL + 1e-20f;
            align_out[(size_t)b * NWORDS + n] = val;
        }
    }
}

/* ------------------- K4: out-proj + tanh — warp-dot, 4096 warps ------- */
/* grid (128, 8). Warp d = bx*4+wp, b-group of 8 per blockIdx.y. W_out   */
/* row (32 regs) stationary; 4-way-unrolled dot chains over [c | src].   */
__global__ void __launch_bounds__(128)
outtanh_kernel(const float* __restrict__ src,
               const float* __restrict__ Wout,
               float* __restrict__ attn_out) {
    const int wp = threadIdx.x >> 5, ln = threadIdx.x & 31;
    const int d = blockIdx.x * 4 + wp;     /* 0..511 */
    const int b0 = blockIdx.y * 8;

    const float4* Wr = (const float4*)(Wout + (size_t)d * (2 * DIM));
    float4 w[8];
    #pragma unroll
    for (int j = 0; j < 8; j++) w[j] = Wr[ln + 32 * j];

    #pragma unroll
    for (int g = 0; g < 2; g++) {
        const int bb = b0 + g * 4;
        float dots[4];
        #pragma unroll
        for (int u = 0; u < 4; u++) {
            const int b = bb + u;
            const float4* C4 = (const float4*)(g_c + (size_t)b * DIM);
            const float4* S4 = (const float4*)(src + (size_t)b * DIM);
            float dsum = 0.f;
            #pragma unroll
            for (int j = 0; j < 4; j++) dsum += dot4(C4[ln + 32 * j], w[j]);
            #pragma unroll
            for (int j = 0; j < 4; j++) dsum += dot4(S4[ln + 32 * j], w[4 + j]);
            dots[u] = dsum;
        }
        #pragma unroll
        for (int u = 0; u < 4; u++) {
            #pragma unroll
            for (int off = 16; off > 0; off >>= 1)
                dots[u] += __shfl_xor_sync(0xffffffffu, dots[u], off);
        }
        if (ln < 4) attn_out[(size_t)(bb + ln) * DIM + d] = tanhf(dots[ln]);
    }
}

/* ------------------- launch ------------------------------------------- */
extern "C" void kernel_launch(void* const* d_in, const int* in_sizes, int n_in,
                              void* d_out, int out_size) {
    const float* source       = (const float*)d_in[0];
    const float* word_bank    = (const float*)d_in[1];
    const int*   word_lengths = (const int*)  d_in[2];
    const float* sent_bank    = (const float*)d_in[3];
    /* d_in[4] = sent_lengths: unused by forward math */
    const float* static_attn  = (const float*)d_in[5];
    const float* W_word       = (const float*)d_in[6];
    const float* W_sent       = (const float*)d_in[7];
    const float* W_out        = (const float*)d_in[8];

    float* attn_out  = (float*)d_out;
    const int need   = BATCH * DIM + BATCH * NWORDS;
    const int has_align = (out_size >= need) ? 1 : 0;
    float* align_out = attn_out + BATCH * DIM;

    cudaFuncSetAttribute(fused_kernel,
                         cudaFuncAttributeMaxDynamicSharedMemorySize, DYN_SMEM);

    qproj_kernel<<<dim3(256, 4), 128>>>(source, W_word, W_sent);         /* 1 */
    fused_kernel<<<dim3(SENTS, BATCH), 128, DYN_SMEM>>>(word_bank,
                     word_lengths, sent_bank, static_attn);              /* 2 */
    combine_kernel<<<dim3(BATCH, 2), 512>>>(word_lengths, align_out,
                                            has_align);                  /* 3 */
    outtanh_kernel<<<dim3(128, 8), 128>>>(source, W_out, attn_out);      /* 4: profiled */
}